// round 16
// baseline (speedup 1.0000x reference)
#include <cuda_runtime.h>
#include <cstdint>

#define BB 2
#define HH 16
#define NS 2048
#define HD 64
#define CD 1024
#define XSIZE (BB*NS*CD)
#define SCALE_F 0.125f
#define HSZ (BB*HH*NS*HD)

// Scratch (allocation-free rule: __device__ globals)
__device__ float g_qh[HSZ];              // (B,H,N,hd)
__device__ float g_kh[HSZ];
__device__ float g_vh[HSZ];
__device__ float g_ao[HSZ];              // attention output before proj
__device__ float g_partial[BB*HH*NS*16]; // per-(row, j-block) exp partial sums
__device__ float g_inv[BB*HH*NS];        // 1 / row sum

__device__ __forceinline__ uint32_t f2tf32(float x) {
    uint32_t y; asm("cvt.rna.tf32.f32 %0, %1;" : "=r"(y) : "f"(x)); return y;
}
__device__ __forceinline__ void tf32_split(float x, uint32_t& hi, uint32_t& lo) {
    hi = f2tf32(x);
    lo = f2tf32(x - __uint_as_float(hi));
}
__device__ __forceinline__ void mma_tf32(float& d0, float& d1, float& d2, float& d3,
                                         uint32_t a0, uint32_t a1, uint32_t a2, uint32_t a3,
                                         uint32_t b0, uint32_t b1) {
    asm volatile(
        "mma.sync.aligned.m16n8k8.row.col.f32.tf32.tf32.f32 "
        "{%0,%1,%2,%3}, {%4,%5,%6,%7}, {%8,%9}, {%0,%1,%2,%3};"
        : "+f"(d0), "+f"(d1), "+f"(d2), "+f"(d3)
        : "r"(a0), "r"(a1), "r"(a2), "r"(a3), "r"(b0), "r"(b1));
}

#define MM_SMEM (2 * 32 * 132 * 4 * 2)   // two double-buffered [2][32][132] arrays

// ---------------------------------------------------------------------------
// TF32 mma.sync GEMM: Y[m,j] = sum_k A[m,k] * W[j,k].  256 thr = 8 warps
// (2 m x 4 n), warp tile 64x32, BM=BN=128, BK=32 (4 mma k-steps).
// Dynamic smem (67.6 KB). MODE 0: qkv. MODE 1: proj (gather + bias).
// ---------------------------------------------------------------------------
template<int MODE>
__global__ __launch_bounds__(256)
void mma_mm(const float* __restrict__ Aq, const float* __restrict__ Ak,
            const float* __restrict__ Av, const float* __restrict__ Wall,
            float* __restrict__ Yq, float* __restrict__ Yk,
            float* __restrict__ Yv, const float* __restrict__ bias)
{
    extern __shared__ uint32_t dsm[];
    uint32_t (*As)[32][132] = (uint32_t(*)[32][132])dsm;              // [2][32][132]
    uint32_t (*Bs)[32][132] = (uint32_t(*)[32][132])(dsm + 2*32*132);

    const int tid  = threadIdx.x;
    const int lane = tid & 31;
    const int warp = tid >> 5;
    const int wm = warp >> 2;            // 0..1
    const int wn = warp & 3;             // 0..3
    const int m0 = blockIdx.y * 128;
    const int n0 = blockIdx.x * 128;

    const float* A;
    const float* W;
    float* Y;
    if (MODE == 0) {
        const int z = blockIdx.z;
        A = (z == 0) ? Aq : (z == 1) ? Ak : Av;
        W = Wall + (size_t)z * CD * CD;
        Y = (z == 0) ? Yq : (z == 1) ? Yk : Yv;
    } else {
        A = Aq; W = Wall; Y = Yq;
    }

    const int r0  = tid >> 3;            // 0..31
    const int kc0 = (tid & 7) << 2;      // 0..28

    int gb[4], gn[4];
    if (MODE == 1) {
#pragma unroll
        for (int v = 0; v < 4; v++) {
            int m = m0 + r0 + 32 * v;
            gb[v] = m >> 11; gn[v] = m & (NS - 1);
        }
    }

    float4 sa[4], sw[4];
    // prologue: tile 0
#pragma unroll
    for (int v = 0; v < 4; v++) {
        int row = r0 + 32 * v;
        if (MODE == 0) {
            sa[v] = *(const float4*)(A + (size_t)(m0 + row) * CD + kc0);
        } else {
            sa[v] = *(const float4*)(A + (((size_t)(gb[v]*HH + (kc0 >> 6)) * NS + gn[v]) * HD + (kc0 & 63)));
        }
        sw[v] = *(const float4*)(W + (size_t)(n0 + row) * CD + kc0);
    }
#pragma unroll
    for (int v = 0; v < 4; v++) {
        int row = r0 + 32 * v;
        As[0][kc0+0][row] = f2tf32(sa[v].x); As[0][kc0+1][row] = f2tf32(sa[v].y);
        As[0][kc0+2][row] = f2tf32(sa[v].z); As[0][kc0+3][row] = f2tf32(sa[v].w);
        Bs[0][kc0+0][row] = f2tf32(sw[v].x); Bs[0][kc0+1][row] = f2tf32(sw[v].y);
        Bs[0][kc0+2][row] = f2tf32(sw[v].z); Bs[0][kc0+3][row] = f2tf32(sw[v].w);
    }

    float acc[4][4][4];
#pragma unroll
    for (int i = 0; i < 4; i++)
#pragma unroll
        for (int j = 0; j < 4; j++)
#pragma unroll
            for (int c = 0; c < 4; c++) acc[i][j][c] = 0.f;

    const int lq = lane & 3;
    const int lr = lane >> 2;

    const int NT = CD / 32;              // 32 k-tiles
    for (int t = 0; t < NT; t++) {
        __syncthreads();
        if (t + 1 < NT) {
            int k = (t + 1) * 32 + kc0;
#pragma unroll
            for (int v = 0; v < 4; v++) {
                int row = r0 + 32 * v;
                if (MODE == 0) {
                    sa[v] = *(const float4*)(A + (size_t)(m0 + row) * CD + k);
                } else {
                    sa[v] = *(const float4*)(A + (((size_t)(gb[v]*HH + (k >> 6)) * NS + gn[v]) * HD + (k & 63)));
                }
                sw[v] = *(const float4*)(W + (size_t)(n0 + row) * CD + k);
            }
        }
        const int cb = t & 1;
#pragma unroll
        for (int ks = 0; ks < 4; ks++) {
            const int kb = ks * 8;
            uint32_t af[4][4], bf[4][2];
#pragma unroll
            for (int i = 0; i < 4; i++) {
                int m = wm * 64 + i * 16 + lr;
                af[i][0] = As[cb][kb + lq    ][m];
                af[i][1] = As[cb][kb + lq    ][m + 8];
                af[i][2] = As[cb][kb + lq + 4][m];
                af[i][3] = As[cb][kb + lq + 4][m + 8];
            }
#pragma unroll
            for (int j = 0; j < 4; j++) {
                int n = wn * 32 + j * 8 + lr;
                bf[j][0] = Bs[cb][kb + lq    ][n];
                bf[j][1] = Bs[cb][kb + lq + 4][n];
            }
#pragma unroll
            for (int i = 0; i < 4; i++)
#pragma unroll
                for (int j = 0; j < 4; j++)
                    mma_tf32(acc[i][j][0], acc[i][j][1], acc[i][j][2], acc[i][j][3],
                             af[i][0], af[i][1], af[i][2], af[i][3],
                             bf[j][0], bf[j][1]);
        }
        if (t + 1 < NT) {
            const int nb = (t + 1) & 1;
#pragma unroll
            for (int v = 0; v < 4; v++) {
                int row = r0 + 32 * v;
                As[nb][kc0+0][row] = f2tf32(sa[v].x); As[nb][kc0+1][row] = f2tf32(sa[v].y);
                As[nb][kc0+2][row] = f2tf32(sa[v].z); As[nb][kc0+3][row] = f2tf32(sa[v].w);
                Bs[nb][kc0+0][row] = f2tf32(sw[v].x); Bs[nb][kc0+1][row] = f2tf32(sw[v].y);
                Bs[nb][kc0+2][row] = f2tf32(sw[v].z); Bs[nb][kc0+3][row] = f2tf32(sw[v].w);
            }
        }
    }

#pragma unroll
    for (int i = 0; i < 4; i++) {
#pragma unroll
        for (int j = 0; j < 4; j++) {
            int col = n0 + wn * 32 + j * 8 + 2 * lq;
            int mA = m0 + wm * 64 + i * 16 + lr;
            int mB = mA + 8;
            float2 v0, v1;
            v0.x = acc[i][j][0]; v0.y = acc[i][j][1];
            v1.x = acc[i][j][2]; v1.y = acc[i][j][3];
            if (MODE == 0) {
                int bA = mA >> 11, nA = mA & (NS - 1);
                int bB = mB >> 11, nB = mB & (NS - 1);
                int head = col >> 6, off = col & 63;
                *(float2*)(Y + (((size_t)(bA*HH + head) * NS + nA) * HD + off)) = v0;
                *(float2*)(Y + (((size_t)(bB*HH + head) * NS + nB) * HD + off)) = v1;
            } else {
                float bx = bias[col], by = bias[col + 1];
                v0.x += bx; v0.y += by;
                v1.x += bx; v1.y += by;
                *(float2*)(Y + (size_t)mA * CD + col) = v0;
                *(float2*)(Y + (size_t)mB * CD + col) = v1;
            }
        }
    }
}

// ---------------------------------------------------------------------------
// Scores on tensor cores with 3xTF32 compensation (unchanged from R13).
// ---------------------------------------------------------------------------
__global__ __launch_bounds__(256)
void score_mma(const float* __restrict__ Q, const float* __restrict__ Kh,
               float* __restrict__ P, float* __restrict__ partial,
               const int* __restrict__ use_mask)
{
    const int bh = blockIdx.z;
    const int m0 = blockIdx.y * 128;
    const int j0 = blockIdx.x * 128;
    const int jblk = blockIdx.x;
    const int tid = threadIdx.x;
    const int lane = tid & 31;
    const int warp = tid >> 5;
    const int wm = warp >> 2;            // 0..1
    const int wn = warp & 3;             // 0..3
    const bool masked = (*use_mask != 0);
    float* Pb = P + (size_t)bh * NS * NS;

    if (masked && j0 > m0 + 127) {
        const int zr = tid >> 1;                 // 0..127
        const int zc = (tid & 1) * 64;
        float4 zer = make_float4(0.f, 0.f, 0.f, 0.f);
#pragma unroll
        for (int c = 0; c < 16; c++)
            *(float4*)(Pb + (size_t)(m0 + zr) * NS + j0 + zc + c * 4) = zer;
        if (tid < 128)
            partial[((size_t)bh * NS + m0 + tid) * 16 + jblk] = 0.f;
        return;
    }

    __shared__ uint32_t Qhi[16][132], Qlo[16][132];
    __shared__ uint32_t KhiS[16][132], KloS[16][132];
    __shared__ float Srow[128][17];

    const float* Qb = Q  + (size_t)bh * NS * HD;
    const float* Kb = Kh + (size_t)bh * NS * HD;

    const int r0  = tid >> 2;            // 0..63
    const int r1  = r0 + 64;
    const int kc0 = (tid & 3) << 2;

    float acc[4][4][4];
#pragma unroll
    for (int i = 0; i < 4; i++)
#pragma unroll
        for (int j = 0; j < 4; j++)
#pragma unroll
            for (int c = 0; c < 4; c++) acc[i][j][c] = 0.f;

    const int lq = lane & 3;
    const int lr = lane >> 2;

#pragma unroll
    for (int t = 0; t < 4; t++) {
        const int k0 = t * 16;
        float4 q0 = *(const float4*)(Qb + (size_t)(m0 + r0) * HD + k0 + kc0);
        float4 q1 = *(const float4*)(Qb + (size_t)(m0 + r1) * HD + k0 + kc0);
        float4 kv0 = *(const float4*)(Kb + (size_t)(j0 + r0) * HD + k0 + kc0);
        float4 kv1 = *(const float4*)(Kb + (size_t)(j0 + r1) * HD + k0 + kc0);
        __syncthreads();                 // prior tile's fragment reads done
        {
            uint32_t h, l;
            tf32_split(q0.x, h, l); Qhi[kc0+0][r0] = h; Qlo[kc0+0][r0] = l;
            tf32_split(q0.y, h, l); Qhi[kc0+1][r0] = h; Qlo[kc0+1][r0] = l;
            tf32_split(q0.z, h, l); Qhi[kc0+2][r0] = h; Qlo[kc0+2][r0] = l;
            tf32_split(q0.w, h, l); Qhi[kc0+3][r0] = h; Qlo[kc0+3][r0] = l;
            tf32_split(q1.x, h, l); Qhi[kc0+0][r1] = h; Qlo[kc0+0][r1] = l;
            tf32_split(q1.y, h, l); Qhi[kc0+1][r1] = h; Qlo[kc0+1][r1] = l;
            tf32_split(q1.z, h, l); Qhi[kc0+2][r1] = h; Qlo[kc0+2][r1] = l;
            tf32_split(q1.w, h, l); Qhi[kc0+3][r1] = h; Qlo[kc0+3][r1] = l;
            tf32_split(kv0.x, h, l); KhiS[kc0+0][r0] = h; KloS[kc0+0][r0] = l;
            tf32_split(kv0.y, h, l); KhiS[kc0+1][r0] = h; KloS[kc0+1][r0] = l;
            tf32_split(kv0.z, h, l); KhiS[kc0+2][r0] = h; KloS[kc0+2][r0] = l;
            tf32_split(kv0.w, h, l); KhiS[kc0+3][r0] = h; KloS[kc0+3][r0] = l;
            tf32_split(kv1.x, h, l); KhiS[kc0+0][r1] = h; KloS[kc0+0][r1] = l;
            tf32_split(kv1.y, h, l); KhiS[kc0+1][r1] = h; KloS[kc0+1][r1] = l;
            tf32_split(kv1.z, h, l); KhiS[kc0+2][r1] = h; KloS[kc0+2][r1] = l;
            tf32_split(kv1.w, h, l); KhiS[kc0+3][r1] = h; KloS[kc0+3][r1] = l;
        }
        __syncthreads();
#pragma unroll
        for (int ks = 0; ks < 2; ks++) {
            const int kb = ks * 8;
            uint32_t ah[4][4], al[4][4], bh2[4][2], bl2[4][2];
#pragma unroll
            for (int i = 0; i < 4; i++) {
                int m = wm * 64 + i * 16 + lr;
                ah[i][0] = Qhi[kb + lq    ][m];
                ah[i][1] = Qhi[kb + lq    ][m + 8];
                ah[i][2] = Qhi[kb + lq + 4][m];
                ah[i][3] = Qhi[kb + lq + 4][m + 8];
                al[i][0] = Qlo[kb + lq    ][m];
                al[i][1] = Qlo[kb + lq    ][m + 8];
                al[i][2] = Qlo[kb + lq + 4][m];
                al[i][3] = Qlo[kb + lq + 4][m + 8];
            }
#pragma unroll
            for (int j = 0; j < 4; j++) {
                int n = wn * 32 + j * 8 + lr;
                bh2[j][0] = KhiS[kb + lq    ][n];
                bh2[j][1] = KhiS[kb + lq + 4][n];
                bl2[j][0] = KloS[kb + lq    ][n];
                bl2[j][1] = KloS[kb + lq + 4][n];
            }
#pragma unroll
            for (int i = 0; i < 4; i++)
#pragma unroll
                for (int j = 0; j < 4; j++) {
                    mma_tf32(acc[i][j][0], acc[i][j][1], acc[i][j][2], acc[i][j][3],
                             ah[i][0], ah[i][1], ah[i][2], ah[i][3],
                             bh2[j][0], bh2[j][1]);
                    mma_tf32(acc[i][j][0], acc[i][j][1], acc[i][j][2], acc[i][j][3],
                             ah[i][0], ah[i][1], ah[i][2], ah[i][3],
                             bl2[j][0], bl2[j][1]);
                    mma_tf32(acc[i][j][0], acc[i][j][1], acc[i][j][2], acc[i][j][3],
                             al[i][0], al[i][1], al[i][2], al[i][3],
                             bh2[j][0], bh2[j][1]);
                }
        }
    }

    // Epilogue: exp + mask + stores + per-row partial sums
#pragma unroll
    for (int i = 0; i < 4; i++) {
        const int rA = wm * 64 + i * 16 + lr;
        const int mGA = m0 + rA;
        const int mGB = mGA + 8;
        float rsA = 0.f, rsB = 0.f;
#pragma unroll
        for (int j = 0; j < 4; j++) {
            int col = j0 + wn * 32 + j * 8 + 2 * lq;
            float e0 = (masked && (col+0) > mGA) ? 0.f : __expf(acc[i][j][0] * SCALE_F);
            float e1 = (masked && (col+1) > mGA) ? 0.f : __expf(acc[i][j][1] * SCALE_F);
            float e2 = (masked && (col+0) > mGB) ? 0.f : __expf(acc[i][j][2] * SCALE_F);
            float e3 = (masked && (col+1) > mGB) ? 0.f : __expf(acc[i][j][3] * SCALE_F);
            rsA += e0 + e1; rsB += e2 + e3;
            float2 v0; v0.x = e0; v0.y = e1;
            float2 v1; v1.x = e2; v1.y = e3;
            *(float2*)(Pb + (size_t)mGA * NS + col) = v0;
            *(float2*)(Pb + (size_t)mGB * NS + col) = v1;
        }
        Srow[rA][wn * 4 + lq]     = rsA;
        Srow[rA + 8][wn * 4 + lq] = rsB;
    }
    __syncthreads();
    if (tid < 128) {
        float s = 0.f;
#pragma unroll
        for (int c = 0; c < 16; c++) s += Srow[tid][c];
        partial[((size_t)bh * NS + m0 + tid) * 16 + jblk] = s;
    }
}

// ---------------------------------------------------------------------------
__global__ __launch_bounds__(256)
void rowinv(const float* __restrict__ partial, float* __restrict__ inv)
{
    int r = blockIdx.x * 256 + threadIdx.x;
    const float4* p = (const float4*)(partial + (size_t)r * 16);
    float4 a = p[0], b = p[1], c = p[2], d = p[3];
    float s = (a.x + a.y + a.z + a.w) + (b.x + b.y + b.z + b.w)
            + (c.x + c.y + c.z + c.w) + (d.x + d.y + d.z + d.w);
    inv[r] = 1.f / s;
}

// ---------------------------------------------------------------------------
// O = softmax(P) @ V on tensor cores (unchanged from R12/R13 best).
// ---------------------------------------------------------------------------
__global__ __launch_bounds__(256)
void av_mma(float* __restrict__ P, const float* __restrict__ V,
            float* __restrict__ O, const float* __restrict__ inv,
            const int* __restrict__ use_mask)
{
    const int bh = blockIdx.y;
    const int m0 = ((int)gridDim.x - 1 - (int)blockIdx.x) * 128;
    const int tid = threadIdx.x;
    const int lane = tid & 31;
    const int warp = tid >> 5;
    const int wm = warp >> 1;            // 0..3
    const int wn = warp & 1;             // 0..1
    const bool masked = (*use_mask != 0);
    const int kmax = masked ? (m0 + 128) : NS;
    const int NT = kmax >> 5;

    __shared__ uint32_t Ps[2][32][132];  // [buf][k][m]
    __shared__ uint32_t Vs[2][32][68];   // [buf][k][n]
    __shared__ float sinv_s[128];

    float* Pb = P + (size_t)bh * NS * NS;
    const float* Vb = V + (size_t)bh * NS * HD;

    if (tid < 128) sinv_s[tid] = inv[(size_t)bh * NS + m0 + tid];

    const int pr0 = tid >> 3;            // 0..31
    const int pr1 = pr0 + 32;
    const int pr2 = pr0 + 64;
    const int pr3 = pr0 + 96;
    const int pkc = (tid & 7) << 2;
    const int vr0 = tid >> 4;            // 0..15  (k row)
    const int vr1 = vr0 + 16;
    const int vc  = (tid & 15) << 2;     // 0..60  (n col)

    float4 sp0, sp1, sp2, sp3, sv0, sv1;
    sp0 = *(const float4*)(Pb + (size_t)(m0 + pr0) * NS + pkc);
    sp1 = *(const float4*)(Pb + (size_t)(m0 + pr1) * NS + pkc);
    sp2 = *(const float4*)(Pb + (size_t)(m0 + pr2) * NS + pkc);
    sp3 = *(const float4*)(Pb + (size_t)(m0 + pr3) * NS + pkc);
    sv0 = *(const float4*)(Vb + (size_t)vr0 * HD + vc);
    sv1 = *(const float4*)(Vb + (size_t)vr1 * HD + vc);
    __syncthreads();                     // sinv_s visible
    {
        Ps[0][pkc+0][pr0] = f2tf32(sp0.x); Ps[0][pkc+1][pr0] = f2tf32(sp0.y);
        Ps[0][pkc+2][pr0] = f2tf32(sp0.z); Ps[0][pkc+3][pr0] = f2tf32(sp0.w);
        Ps[0][pkc+0][pr1] = f2tf32(sp1.x); Ps[0][pkc+1][pr1] = f2tf32(sp1.y);
        Ps[0][pkc+2][pr1] = f2tf32(sp1.z); Ps[0][pkc+3][pr1] = f2tf32(sp1.w);
        Ps[0][pkc+0][pr2] = f2tf32(sp2.x); Ps[0][pkc+1][pr2] = f2tf32(sp2.y);
        Ps[0][pkc+2][pr2] = f2tf32(sp2.z); Ps[0][pkc+3][pr2] = f2tf32(sp2.w);
        Ps[0][pkc+0][pr3] = f2tf32(sp3.x); Ps[0][pkc+1][pr3] = f2tf32(sp3.y);
        Ps[0][pkc+2][pr3] = f2tf32(sp3.z); Ps[0][pkc+3][pr3] = f2tf32(sp3.w);
        Vs[0][vr0][vc+0] = f2tf32(sv0.x); Vs[0][vr0][vc+1] = f2tf32(sv0.y);
        Vs[0][vr0][vc+2] = f2tf32(sv0.z); Vs[0][vr0][vc+3] = f2tf32(sv0.w);
        Vs[0][vr1][vc+0] = f2tf32(sv1.x); Vs[0][vr1][vc+1] = f2tf32(sv1.y);
        Vs[0][vr1][vc+2] = f2tf32(sv1.z); Vs[0][vr1][vc+3] = f2tf32(sv1.w);
        float s0 = sinv_s[pr0], s1 = sinv_s[pr1], s2 = sinv_s[pr2], s3 = sinv_s[pr3];
        float4 w;
        w.x = sp0.x*s0; w.y = sp0.y*s0; w.z = sp0.z*s0; w.w = sp0.w*s0;
        *(float4*)(Pb + (size_t)(m0 + pr0) * NS + pkc) = w;
        w.x = sp1.x*s1; w.y = sp1.y*s1; w.z = sp1.z*s1; w.w = sp1.w*s1;
        *(float4*)(Pb + (size_t)(m0 + pr1) * NS + pkc) = w;
        w.x = sp2.x*s2; w.y = sp2.y*s2; w.z = sp2.z*s2; w.w = sp2.w*s2;
        *(float4*)(Pb + (size_t)(m0 + pr2) * NS + pkc) = w;
        w.x = sp3.x*s3; w.y = sp3.y*s3; w.z = sp3.z*s3; w.w = sp3.w*s3;
        *(float4*)(Pb + (size_t)(m0 + pr3) * NS + pkc) = w;
    }

    float acc[2][4][4];
#pragma unroll
    for (int i = 0; i < 2; i++)
#pragma unroll
        for (int j = 0; j < 4; j++)
#pragma unroll
            for (int c = 0; c < 4; c++) acc[i][j][c] = 0.f;

    const int lq = lane & 3;
    const int lr = lane >> 2;

    for (int t = 0; t < NT; t++) {
        __syncthreads();
        if (t + 1 < NT) {
            int kk0 = (t + 1) * 32;
            sp0 = *(const float4*)(Pb + (size_t)(m0 + pr0) * NS + kk0 + pkc);
            sp1 = *(const float4*)(Pb + (size_t)(m0 + pr1) * NS + kk0 + pkc);
            sp2 = *(const float4*)(Pb + (size_t)(m0 + pr2) * NS + kk0 + pkc);
            sp3 = *(const float4*)(Pb + (size_t)(m0 + pr3) * NS + kk0 + pkc);
            sv0 = *(const float4*)(Vb + (size_t)(kk0 + vr0) * HD + vc);
            sv1 = *(const float4*)(Vb + (size_t)(kk0 + vr1) * HD + vc);
        }
        const int cb = t & 1;
#pragma unroll
        for (int ks = 0; ks < 4; ks++) {
            const int kb = ks * 8;
            uint32_t af[2][4], bf[4][2];
#pragma unroll
            for (int i = 0; i < 2; i++) {
                int m = wm * 32 + i * 16 + lr;
                af[i][0] = Ps[cb][kb + lq    ][m];
                af[i][1] = Ps[cb][kb + lq    ][m + 8];
                af[i][2] = Ps[cb][kb + lq + 4][m];
                af[i][3] = Ps[cb][kb + lq + 4][m + 8];
            }
#pragma unroll
            for (int j = 0; j < 4; j++) {
                int n = wn * 32 + j * 8 + lr;
                bf[j][0] = Vs[cb][kb + lq    ][n];
                bf[j][1] = Vs[cb][kb + lq + 4][n];
            }
#pragma unroll
            for (int i = 0; i < 2; i++)
#pragma unroll
                for (int j = 0; j < 4; j++)
                    mma_tf32(acc[i][j][0], acc[i][j][1], acc[i][j][2], acc[i][j][3],
                             af[i][0], af[i][1], af[i][2], af[i][3],
                             bf[j][0], bf[j][1]);
        }
        if (t + 1 < NT) {
            const int nb = (t + 1) & 1;
            const int kk0 = (t + 1) * 32;
            Ps[nb][pkc+0][pr0] = f2tf32(sp0.x); Ps[nb][pkc+1][pr0] = f2tf32(sp0.y);
            Ps[nb][pkc+2][pr0] = f2tf32(sp0.z); Ps[nb][pkc+3][pr0] = f2tf32(sp0.w);
            Ps[nb][pkc+0][pr1] = f2tf32(sp1.x); Ps[nb][pkc+1][pr1] = f2tf32(sp1.y);
            Ps[nb][pkc+2][pr1] = f2tf32(sp1.z); Ps[nb][pkc+3][pr1] = f2tf32(sp1.w);
            Ps[nb][pkc+0][pr2] = f2tf32(sp2.x); Ps[nb][pkc+1][pr2] = f2tf32(sp2.y);
            Ps[nb][pkc+2][pr2] = f2tf32(sp2.z); Ps[nb][pkc+3][pr2] = f2tf32(sp2.w);
            Ps[nb][pkc+0][pr3] = f2tf32(sp3.x); Ps[nb][pkc+1][pr3] = f2tf32(sp3.y);
            Ps[nb][pkc+2][pr3] = f2tf32(sp3.z); Ps[nb][pkc+3][pr3] = f2tf32(sp3.w);
            Vs[nb][vr0][vc+0] = f2tf32(sv0.x); Vs[nb][vr0][vc+1] = f2tf32(sv0.y);
            Vs[nb][vr0][vc+2] = f2tf32(sv0.z); Vs[nb][vr0][vc+3] = f2tf32(sv0.w);
            Vs[nb][vr1][vc+0] = f2tf32(sv1.x); Vs[nb][vr1][vc+1] = f2tf32(sv1.y);
            Vs[nb][vr1][vc+2] = f2tf32(sv1.z); Vs[nb][vr1][vc+3] = f2tf32(sv1.w);
            float s0 = sinv_s[pr0], s1 = sinv_s[pr1], s2 = sinv_s[pr2], s3 = sinv_s[pr3];
            float4 w;
            w.x = sp0.x*s0; w.y = sp0.y*s0; w.z = sp0.z*s0; w.w = sp0.w*s0;
            *(float4*)(Pb + (size_t)(m0 + pr0) * NS + kk0 + pkc) = w;
            w.x = sp1.x*s1; w.y = sp1.y*s1; w.z = sp1.z*s1; w.w = sp1.w*s1;
            *(float4*)(Pb + (size_t)(m0 + pr1) * NS + kk0 + pkc) = w;
            w.x = sp2.x*s2; w.y = sp2.y*s2; w.z = sp2.z*s2; w.w = sp2.w*s2;
            *(float4*)(Pb + (size_t)(m0 + pr2) * NS + kk0 + pkc) = w;
            w.x = sp3.x*s3; w.y = sp3.y*s3; w.z = sp3.z*s3; w.w = sp3.w*s3;
            *(float4*)(Pb + (size_t)(m0 + pr3) * NS + kk0 + pkc) = w;
        }
    }

#pragma unroll
    for (int i = 0; i < 2; i++) {
#pragma unroll
        for (int j = 0; j < 4; j++) {
            int col = wn * 32 + j * 8 + 2 * lq;
            int lmA = wm * 32 + i * 16 + lr;
            int lmB = lmA + 8;
            float sA = sinv_s[lmA], sB = sinv_s[lmB];
            float2 v0, v1;
            v0.x = acc[i][j][0] * sA; v0.y = acc[i][j][1] * sA;
            v1.x = acc[i][j][2] * sB; v1.y = acc[i][j][3] * sB;
            *(float2*)(O + ((size_t)bh * NS + m0 + lmA) * HD + col) = v0;
            *(float2*)(O + ((size_t)bh * NS + m0 + lmB) * HD + col) = v1;
        }
    }
}

// ---------------------------------------------------------------------------
extern "C" void kernel_launch(void* const* d_in, const int* in_sizes, int n_in,
                              void* d_out, int out_size)
{
    const float* q      = (const float*)d_in[0];
    const float* k      = (const float*)d_in[1];
    const float* v      = (const float*)d_in[2];
    const float* qkv_w  = (const float*)d_in[3];
    const float* proj_w = (const float*)d_in[4];
    const float* proj_b = (const float*)d_in[5];
    const int*   use_mask = (const int*)d_in[6];

    float* out      = (float*)d_out;
    float* x_out    = out;                       // (B, N, C)
    float* attn_out = out + (size_t)XSIZE;       // (B, H, N, N)

    float *qh, *kh, *vh, *ao, *part, *invs;
    cudaGetSymbolAddress((void**)&qh, g_qh);
    cudaGetSymbolAddress((void**)&kh, g_kh);
    cudaGetSymbolAddress((void**)&vh, g_vh);
    cudaGetSymbolAddress((void**)&ao, g_ao);
    cudaGetSymbolAddress((void**)&part, g_partial);
    cudaGetSymbolAddress((void**)&invs, g_inv);

    // >48KB dynamic smem opt-in (host-side config call; capture-safe, no guards)
    cudaFuncSetAttribute(mma_mm<0>, cudaFuncAttributeMaxDynamicSharedMemorySize, MM_SMEM);
    cudaFuncSetAttribute(mma_mm<1>, cudaFuncAttributeMaxDynamicSharedMemorySize, MM_SMEM);

    dim3 blk(256);

    // QKV projections on tensor cores (BK=32, dynamic smem)
    mma_mm<0><<<dim3(CD/128, (BB*NS)/128, 3), blk, MM_SMEM>>>(
        q, k, v, qkv_w, qh, kh, vh, nullptr);

    // exp(scale * Q K^T) with mask on tensor cores (3xTF32) + partial sums
    score_mma<<<dim3(NS/128, NS/128, BB*HH), blk>>>(qh, kh, attn_out, part, use_mask);

    // Row inverse sums
    rowinv<<<(BB*HH*NS)/256, blk>>>(part, invs);

    // Normalize P (finalizing attn output) + P @ V on tensor cores
    av_mma<<<dim3(NS/128, BB*HH), blk>>>(attn_out, vh, ao, invs, use_mask);

    // Output projection + bias on tensor cores (BK=32, dynamic smem)
    mma_mm<1><<<dim3(CD/128, (BB*NS)/128, 1), blk, MM_SMEM>>>(
        ao, nullptr, nullptr, proj_w, x_out, nullptr, nullptr, proj_b);
}